// round 3
// baseline (speedup 1.0000x reference)
#include <cuda_runtime.h>
#include <math.h>

// Shapes
#define BN   4096   // patients
#define DD   19     // feature dim
#define FF   64     // averaged dim
#define NCC  256    // centers
#define NTOT 4352   // BN + NCC
#define HIDD 32
#define SQH  16

// Scratch (device globals: no allocation allowed)
__device__ float g_xa[NTOT * DD];      // x_all (x_avg rows then centers_p rows)
__device__ float g_e [NTOT * DD];      // exp(1 - dc_all)
__device__ float g_sq[NTOT];           // row squared norms
__device__ float g_h [NTOT * HIDD];    // x_all @ gcn_w
__device__ float g_embpre[NCC * HIDD]; // adj[b+j,:] @ h   (accumulated)
__device__ float g_ge [NCC * DD];      // group_embedding
__device__ float g_spg[NCC * DD];      // scores_per_group
__device__ int   g_label[BN];

// ---------------------------------------------------------------------------
// Kernel A: x_avg. One warp per 2 rows (128 contiguous floats); each lane
// loads one float4 -> a single fully-coalesced 512B segment per warp.
// 77824 rows -> 38912 warps -> 4864 blocks * 8 warps.
__global__ void k_xavg(const float* __restrict__ x) {
    int w    = blockIdx.x * 8 + (threadIdx.x >> 5);
    int lane = threadIdx.x & 31;
    const float4* p = (const float4*)(x + (size_t)w * 128);
    float4 v = p[lane];
    float s = (v.x + v.y) + (v.z + v.w);
    // reduce within each 16-lane half (one half per row)
    s += __shfl_xor_sync(0xffffffffu, s, 8);
    s += __shfl_xor_sync(0xffffffffu, s, 4);
    s += __shfl_xor_sync(0xffffffffu, s, 2);
    s += __shfl_xor_sync(0xffffffffu, s, 1);
    if ((lane & 15) == 0) g_xa[w * 2 + (lane >> 4)] = s * (1.0f / 64.0f);
}

// ---------------------------------------------------------------------------
// Kernel B (merged prep): blocks 0..15 -> patients (sq/e/h from x_avg);
// block 16 -> centers (proj, sq/e/h, zero g_embpre). 17 blocks * 256.
__global__ void k_prep(const float* __restrict__ dc,
                       const float* __restrict__ gcn_w,
                       const float* __restrict__ centers,
                       const float* __restrict__ proj_w,
                       const float* __restrict__ proj_b,
                       const float* __restrict__ cc) {
    __shared__ float sw[DD * HIDD];
    __shared__ float spw[61 * DD];
    __shared__ float spb[DD];
    int t = threadIdx.x;
    for (int i = t; i < DD * HIDD; i += 256) sw[i] = gcn_w[i];

    if (blockIdx.x < 16) {
        __syncthreads();
        int i = blockIdx.x * 256 + t;
        float xa[DD]; float sq = 0.f;
        #pragma unroll
        for (int d = 0; d < DD; d++) { xa[d] = g_xa[i * DD + d]; sq += xa[d] * xa[d]; }
        g_sq[i] = sq;
        #pragma unroll
        for (int d = 0; d < DD; d++) g_e[i * DD + d] = expf(1.0f - dc[i * DD + d]);
        #pragma unroll
        for (int c = 0; c < HIDD; c++) {
            float a = 0.f;
            #pragma unroll
            for (int d = 0; d < DD; d++) a += xa[d] * sw[d * HIDD + c];
            g_h[i * HIDD + c] = a;
        }
        return;
    }

    // centers block
    for (int i = t; i < 61 * DD; i += 256) spw[i] = proj_w[i];
    if (t < DD) spb[t] = proj_b[t];
    __syncthreads();

    int j = t;
    float cp[DD];
    #pragma unroll
    for (int d = 0; d < DD; d++) cp[d] = spb[d];
    for (int k = 0; k < 61; k++) {
        float cv = centers[j * 61 + k];
        #pragma unroll
        for (int d = 0; d < DD; d++) cp[d] += cv * spw[k * DD + d];
    }
    float sq = 0.f;
    #pragma unroll
    for (int d = 0; d < DD; d++) { g_xa[(BN + j) * DD + d] = cp[d]; sq += cp[d] * cp[d]; }
    g_sq[BN + j] = sq;
    #pragma unroll
    for (int d = 0; d < DD; d++) g_e[(BN + j) * DD + d] = expf(1.0f - cc[j * DD + d]);
    #pragma unroll
    for (int c = 0; c < HIDD; c++) {
        float a = 0.f;
        #pragma unroll
        for (int d = 0; d < DD; d++) a += cp[d] * sw[d * HIDD + c];
        g_h[(BN + j) * HIDD + c] = a;
        g_embpre[j * HIDD + c]   = 0.f;
    }
}

// ---------------------------------------------------------------------------
// Kernel CD (fused): independent siblings after k_prep, run concurrently.
//
// Blocks [0,128):   argmax part. group_label = argmax_j sim(i,j) == argmin_j
//   t(i,j) (sim = d/t, t>0, strictly monotone decreasing; first-index ties).
//   Block = 32 patients x 8 j-groups of 32; center table in smem.
//
// Blocks [128,384): emb part. emb_pre[j,:] += adj[b+j, kslice] @ h[kslice,:]
//   u = blockIdx.x-128: j-tile = u>>3 (8 centers), k-split = u&7 (544 nodes).
//   Warp w owns center j0+w; lanes stride nodes; warp-reduce + atomicAdd.
__global__ void k_argmax_emb(const float* __restrict__ pparam) {
    int t = threadIdx.x;
    float pm = *pparam, om = 1.0f - pm;

    if (blockIdx.x < 128) {
        __shared__ float s_cp[NCC * DD];
        __shared__ float s_ec[NCC * DD];
        __shared__ float s_sq[NCC];
        __shared__ float s_bv[256];
        __shared__ int   s_bi[256];
        for (int i = t; i < NCC * DD; i += 256) {
            s_cp[i] = g_xa[BN * DD + i];
            s_ec[i] = g_e [BN * DD + i];
        }
        if (t < NCC) s_sq[t] = g_sq[BN + t];
        __syncthreads();

        int pi = t & 31, jg = t >> 5;
        int i = blockIdx.x * 32 + pi;
        float xa[DD], ee[DD];
        #pragma unroll
        for (int d = 0; d < DD; d++) { xa[d] = g_xa[i * DD + d]; ee[d] = g_e[i * DD + d]; }
        float sqi = g_sq[i];

        float best = 3.4e38f; int bidx = jg * 32;
        for (int j = jg * 32; j < jg * 32 + 32; j++) {
            float dot = 0.f, edot = 0.f;
            #pragma unroll
            for (int d = 0; d < DD; d++) {
                dot  += xa[d] * s_cp[j * DD + d];
                edot += ee[d] * s_ec[j * DD + d];
            }
            float sqd = sqi + s_sq[j] - 2.0f * dot;
            float tt  = om * sqd + pm * edot;
            if (tt < best) { best = tt; bidx = j; }
        }
        s_bv[t] = best; s_bi[t] = bidx;
        __syncthreads();
        if (jg == 0) {
            float b = s_bv[pi]; int bi = s_bi[pi];
            #pragma unroll
            for (int g = 1; g < 8; g++) {
                float v = s_bv[g * 32 + pi]; int vi = s_bi[g * 32 + pi];
                if (v < b || (v == b && vi < bi)) { b = v; bi = vi; }
            }
            g_label[i] = bi;
        }
        return;
    }

    // ---- emb part ----
    __shared__ float s_c[8][2 * DD + 1];
    int u  = blockIdx.x - 128;
    int j0 = (u >> 3) * 8;
    int k0 = (u & 7) * 544;
    for (int i = t; i < 8 * (2 * DD + 1); i += 256) {
        int jl = i / (2 * DD + 1), f = i % (2 * DD + 1);
        float v;
        if      (f < DD)      v = g_xa[(BN + j0 + jl) * DD + f];
        else if (f < 2 * DD)  v = g_e [(BN + j0 + jl) * DD + (f - DD)];
        else                  v = g_sq[BN + j0 + jl];
        s_c[jl][f] = v;
    }
    __syncthreads();

    int w = t >> 5, lane = t & 31;
    int j = j0 + w;
    float cp[DD], ec[DD];
    #pragma unroll
    for (int d = 0; d < DD; d++) { cp[d] = s_c[w][d]; ec[d] = s_c[w][DD + d]; }
    float sqc = s_c[w][2 * DD];

    float acc[HIDD];
    #pragma unroll
    for (int c = 0; c < HIDD; c++) acc[c] = 0.f;

    for (int it = 0; it < 17; it++) {
        int k = k0 + it * 32 + lane;
        const float* xr = &g_xa[k * DD];
        const float* er = &g_e [k * DD];
        float dot = 0.f, edot = 0.f;
        #pragma unroll
        for (int d = 0; d < DD; d++) { dot += cp[d] * xr[d]; edot += ec[d] * er[d]; }
        float a;
        if (k == BN + j) {
            a = 1.0f;                           // eye term
        } else {
            float sqd   = sqc + g_sq[k] - 2.0f * dot;
            float tt    = om * sqd + pm * edot;
            float denom = tt / 19.0f;           // match reference arithmetic
            a = 1.0f / denom;
        }
        const float4* hr = (const float4*)&g_h[k * HIDD];
        #pragma unroll
        for (int q = 0; q < 8; q++) {
            float4 hv = hr[q];
            acc[q * 4 + 0] += a * hv.x; acc[q * 4 + 1] += a * hv.y;
            acc[q * 4 + 2] += a * hv.z; acc[q * 4 + 3] += a * hv.w;
        }
    }
    #pragma unroll
    for (int c = 0; c < HIDD; c++) {
        float v = acc[c];
        #pragma unroll
        for (int o = 16; o; o >>= 1) v += __shfl_xor_sync(0xffffffffu, v, o);
        if (lane == 0) atomicAdd(&g_embpre[j * HIDD + c], v);
    }
}

// ---------------------------------------------------------------------------
// Kernel E: heads. group_embedding = sigmoid((emb_pre+gcn_b)@out_w+out_b),
// scores = sigmoid(gelu_exact(ge@imp_w1+b1)@imp_w2+b2). One block, 256 thr.
__global__ void k_head(const float* __restrict__ gcn_b,
                       const float* __restrict__ out_w, const float* __restrict__ out_b,
                       const float* __restrict__ iw1, const float* __restrict__ ib1,
                       const float* __restrict__ iw2, const float* __restrict__ ib2) {
    int j = threadIdx.x;
    float v[HIDD];
    #pragma unroll
    for (int c = 0; c < HIDD; c++) v[c] = g_embpre[j * HIDD + c] + gcn_b[c];
    float ge[DD];
    #pragma unroll
    for (int d = 0; d < DD; d++) {
        float s = out_b[d];
        #pragma unroll
        for (int c = 0; c < HIDD; c++) s += v[c] * out_w[c * DD + d];
        ge[d] = 1.0f / (1.0f + expf(-s));
        g_ge[j * DD + d] = ge[d];
    }
    float h2[SQH];
    #pragma unroll
    for (int q = 0; q < SQH; q++) {
        float s = ib1[q];
        #pragma unroll
        for (int d = 0; d < DD; d++) s += ge[d] * iw1[d * SQH + q];
        h2[q] = 0.5f * s * (1.0f + erff(s * 0.70710678118654752440f)); // exact gelu
    }
    #pragma unroll
    for (int d = 0; d < DD; d++) {
        float s = ib2[d];
        #pragma unroll
        for (int q = 0; q < SQH; q++) s += h2[q] * iw2[q * DD + d];
        g_spg[j * DD + d] = 1.0f / (1.0f + expf(-s));
    }
}

// ---------------------------------------------------------------------------
// Kernel F: write flattened output tuple:
// [group_scores (4096*19) | group_embedding (256*19) |
//  group_patients_embedding (4096*19) | group_label (4096, as float)]
__global__ void k_out(float* __restrict__ out) {
    int t = blockIdx.x * 256 + threadIdx.x;
    if (t >= 164608) return;
    if (t < 77824) {
        int i = t / 19, d = t - i * 19;
        out[t] = g_spg[g_label[i] * DD + d];
    } else if (t < 82688) {
        out[t] = g_ge[t - 77824];
    } else if (t < 160512) {
        int u = t - 82688; int i = u / 19, d = u - i * 19;
        out[t] = g_ge[g_label[i] * DD + d];
    } else {
        out[t] = (float)g_label[t - 160512];
    }
}

// ---------------------------------------------------------------------------
extern "C" void kernel_launch(void* const* d_in, const int* in_sizes, int n_in,
                              void* d_out, int out_size) {
    const float* x       = (const float*)d_in[0];
    const float* dc      = (const float*)d_in[1];
    const float* centers = (const float*)d_in[2];
    const float* proj_w  = (const float*)d_in[3];
    const float* proj_b  = (const float*)d_in[4];
    const float* dcp     = (const float*)d_in[5];
    const float* cc      = (const float*)d_in[6];
    const float* gcn_w   = (const float*)d_in[7];
    const float* gcn_b   = (const float*)d_in[8];
    const float* out_w   = (const float*)d_in[9];
    const float* out_b   = (const float*)d_in[10];
    const float* iw1     = (const float*)d_in[11];
    const float* ib1     = (const float*)d_in[12];
    const float* iw2     = (const float*)d_in[13];
    const float* ib2     = (const float*)d_in[14];
    float* out = (float*)d_out;

    k_xavg      <<<4864, 256>>>(x);
    k_prep      <<<17,   256>>>(dc, gcn_w, centers, proj_w, proj_b, cc);
    k_argmax_emb<<<384,  256>>>(dcp);
    k_head      <<<1,    256>>>(gcn_b, out_w, out_b, iw1, ib1, iw2, ib2);
    k_out       <<<644,  256>>>(out);
}

// round 9
// speedup vs baseline: 2.3478x; 2.3478x over previous
#include <cuda_runtime.h>
#include <math.h>

// Shapes
#define BN   4096
#define DD   19
#define FF   64
#define NCC  256
#define NTOT 4352
#define HIDD 32
#define SQH  16

// Transposed node tables: [feature][node] so per-node lane access is coalesced.
__device__ float g_xaT[DD * NTOT];
__device__ float g_eT [DD * NTOT];
__device__ float g_sq [NTOT];
__device__ float g_hT [HIDD * NTOT];
__device__ float g_embpreT[HIDD * NCC];  // [c][j]
__device__ float g_geT [DD * NCC];       // [d][j]
__device__ float g_spgT[DD * NCC];       // [d][j]
__device__ int   g_label[BN];
__device__ int   g_ctr;

// ---------------------------------------------------------------------------
// k_xavg: blocks [0,4864): x_avg — warp = 2 rows (128 contiguous floats),
//   lane = one float4; writes g_xaT[d*NTOT+b].
// blocks [4864,4880): patient e-table (x-independent, overlaps the x sweep).
// block 4880: full centers pipeline (x-independent) + zero embpre + ctr.
__global__ void k_xavg(const float* __restrict__ x,
                       const float* __restrict__ dc,
                       const float* __restrict__ centers,
                       const float* __restrict__ proj_w,
                       const float* __restrict__ proj_b,
                       const float* __restrict__ cc,
                       const float* __restrict__ gcn_w) {
    __shared__ float pool[4883];
    int t = threadIdx.x;

    if (blockIdx.x < 4864) {
        int w    = blockIdx.x * 8 + (t >> 5);
        int lane = t & 31;
        const float4* p = (const float4*)(x + (size_t)w * 128);
        float4 v = p[lane];
        float s = (v.x + v.y) + (v.z + v.w);
        s += __shfl_xor_sync(0xffffffffu, s, 8);
        s += __shfl_xor_sync(0xffffffffu, s, 4);
        s += __shfl_xor_sync(0xffffffffu, s, 2);
        s += __shfl_xor_sync(0xffffffffu, s, 1);
        if ((lane & 15) == 0) {
            int r = w * 2 + (lane >> 4);
            int b = r / DD, d = r - b * DD;
            g_xaT[d * NTOT + b] = s * (1.0f / 64.0f);
        }
        return;
    }

    int eb = blockIdx.x - 4864;
    if (eb < 16) {
        // patient e-table: e[d][i] = exp(1 - dc[i][d]), coalesced both sides
        float* s_dc = pool;                       // 4864 floats
        int base = eb * 256;
        for (int i = t; i < 256 * DD; i += 256) s_dc[i] = dc[base * DD + i];
        __syncthreads();
        int i = base + t;
        #pragma unroll
        for (int d = 0; d < DD; d++)
            g_eT[d * NTOT + i] = expf(1.0f - s_dc[t * DD + d]);
        return;
    }

    // centers block: proj -> xaT/sq/eT/hT for nodes BN..BN+255; zero embpre.
    float* spw = pool;           // 61*19 = 1159
    float* spb = pool + 1159;    // 19
    float* sw  = pool + 1178;    // 19*32 = 608
    for (int i = t; i < 61 * DD; i += 256) spw[i] = proj_w[i];
    for (int i = t; i < DD * HIDD; i += 256) sw[i] = gcn_w[i];
    if (t < DD) spb[t] = proj_b[t];
    if (t == 0) g_ctr = 0;
    __syncthreads();

    int j = t;
    float cp[DD];
    #pragma unroll
    for (int d = 0; d < DD; d++) cp[d] = spb[d];
    for (int k = 0; k < 61; k++) {
        float cv = centers[j * 61 + k];
        #pragma unroll
        for (int d = 0; d < DD; d++) cp[d] += cv * spw[k * DD + d];
    }
    float sq = 0.f;
    #pragma unroll
    for (int d = 0; d < DD; d++) { g_xaT[d * NTOT + BN + j] = cp[d]; sq += cp[d] * cp[d]; }
    g_sq[BN + j] = sq;
    #pragma unroll
    for (int d = 0; d < DD; d++) g_eT[d * NTOT + BN + j] = expf(1.0f - cc[j * DD + d]);
    #pragma unroll
    for (int c = 0; c < HIDD; c++) {
        float a = 0.f;
        #pragma unroll
        for (int d = 0; d < DD; d++) a += cp[d] * sw[d * HIDD + c];
        g_hT[c * NTOT + BN + j] = a;
    }
    for (int i = t; i < NCC * HIDD; i += 256) g_embpreT[i] = 0.f;
}

// ---------------------------------------------------------------------------
// k_prep2: patient sq + h (needs complete x_avg). 16 blocks * 256.
__global__ void k_prep2(const float* __restrict__ gcn_w) {
    __shared__ float sw[DD * HIDD];
    int t = threadIdx.x;
    for (int i = t; i < DD * HIDD; i += 256) sw[i] = gcn_w[i];
    __syncthreads();
    int i = blockIdx.x * 256 + t;
    float xa[DD]; float sq = 0.f;
    #pragma unroll
    for (int d = 0; d < DD; d++) { xa[d] = g_xaT[d * NTOT + i]; sq += xa[d] * xa[d]; }
    g_sq[i] = sq;
    #pragma unroll
    for (int c = 0; c < HIDD; c++) {
        float a = 0.f;
        #pragma unroll
        for (int d = 0; d < DD; d++) a += xa[d] * sw[d * HIDD + c];
        g_hT[c * NTOT + i] = a;
    }
}

// ---------------------------------------------------------------------------
// Fused argmax + emb (+ heads tail). Both depend only on prep.
//
// Blocks [0,128):   emb. Block = 16 centers (2/warp) x 544-node k-slice;
//   node chunks (32 x 71 feats) double-buffered in smem pool; warp-reduce +
//   atomicAdd into g_embpreT. Last emb block (atomic count) runs the heads.
//
// Blocks [128,256): argmax. label[i] = argmax_j sim == argmin_j t (t>0,
//   monotone decreasing 1/x; first-index ties both sides).
#define CHUNK (71 * 32)
#define POOL  10496
__global__ void __launch_bounds__(256, 1)
k_argmax_emb(const float* __restrict__ pparam,
             const float* __restrict__ gcn_b,
             const float* __restrict__ out_w, const float* __restrict__ out_b,
             const float* __restrict__ iw1, const float* __restrict__ ib1,
             const float* __restrict__ iw2, const float* __restrict__ ib2) {
    __shared__ float pool[POOL];
    __shared__ int   s_last;
    int t = threadIdx.x;
    float pm = *pparam, om = 1.0f - pm;

    if (blockIdx.x >= 128) {
        // ---------------- argmax ----------------
        float* s_cp = pool;                 // NCC*DD
        float* s_ec = pool + 4864;          // NCC*DD
        float* s_sq = pool + 9728;          // NCC
        float* s_bv = pool + 9984;          // 256
        int*   s_bi = (int*)(pool + 10240); // 256
        for (int idx = t; idx < NCC * DD; idx += 256) {
            int d = idx >> 8, j = idx & 255;
            s_cp[j * DD + d] = g_xaT[d * NTOT + BN + j];
            s_ec[j * DD + d] = g_eT [d * NTOT + BN + j];
        }
        if (t < NCC) s_sq[t] = g_sq[BN + t];
        __syncthreads();

        int pi = t & 31, jg = t >> 5;
        int i = (blockIdx.x - 128) * 32 + pi;
        float xa[DD], ee[DD];
        #pragma unroll
        for (int d = 0; d < DD; d++) { xa[d] = g_xaT[d * NTOT + i]; ee[d] = g_eT[d * NTOT + i]; }
        float sqi = g_sq[i];

        float best = 3.4e38f; int bidx = jg * 32;
        for (int j = jg * 32; j < jg * 32 + 32; j++) {
            float dot = 0.f, edot = 0.f;
            #pragma unroll
            for (int d = 0; d < DD; d++) {
                dot  += xa[d] * s_cp[j * DD + d];
                edot += ee[d] * s_ec[j * DD + d];
            }
            float sqd = sqi + s_sq[j] - 2.0f * dot;
            float tt  = om * sqd + pm * edot;
            if (tt < best) { best = tt; bidx = j; }
        }
        s_bv[t] = best; s_bi[t] = bidx;
        __syncthreads();
        if (jg == 0) {
            float b = s_bv[pi]; int bi = s_bi[pi];
            #pragma unroll
            for (int g = 1; g < 8; g++) {
                float v = s_bv[g * 32 + pi]; int vi = s_bi[g * 32 + pi];
                if (v < b || (v == b && vi < bi)) { b = v; bi = vi; }
            }
            g_label[i] = bi;
        }
        return;
    }

    // ---------------- emb ----------------
    float* buf0 = pool;
    float* buf1 = pool + CHUNK;
    int w = t >> 5, lane = t & 31;
    int u = blockIdx.x;
    int j0 = (u >> 3) * 16;
    int k0 = (u & 7) * 544;
    int ja = j0 + 2 * w, jb = ja + 1;

    float cp1[DD], ec1[DD], cp2[DD], ec2[DD];
    #pragma unroll
    for (int d = 0; d < DD; d++) {
        cp1[d] = g_xaT[d * NTOT + BN + ja];  cp2[d] = g_xaT[d * NTOT + BN + jb];
        ec1[d] = g_eT [d * NTOT + BN + ja];  ec2[d] = g_eT [d * NTOT + BN + jb];
    }
    float sq1 = g_sq[BN + ja], sq2 = g_sq[BN + jb];

    float acc1[HIDD], acc2[HIDD];
    #pragma unroll
    for (int c = 0; c < HIDD; c++) { acc1[c] = 0.f; acc2[c] = 0.f; }

    #pragma unroll
    for (int q = 0; q < 9; q++) {
        int idx = t + q * 256;
        if (idx < CHUNK) {
            int f = idx >> 5, n = idx & 31;
            float v;
            if      (f < DD)      v = g_xaT[f * NTOT + k0 + n];
            else if (f < 2 * DD)  v = g_eT [(f - DD) * NTOT + k0 + n];
            else if (f < 70)      v = g_hT [(f - 2 * DD) * NTOT + k0 + n];
            else                  v = g_sq [k0 + n];
            buf0[idx] = v;
        }
    }
    __syncthreads();

    for (int it = 0; it < 17; it++) {
        float* cur = (it & 1) ? buf1 : buf0;
        float* nxt = (it & 1) ? buf0 : buf1;
        float r[9];
        if (it < 16) {
            int kb = k0 + (it + 1) * 32;
            #pragma unroll
            for (int q = 0; q < 9; q++) {
                int idx = t + q * 256;
                if (idx < CHUNK) {
                    int f = idx >> 5, n = idx & 31;
                    if      (f < DD)      r[q] = g_xaT[f * NTOT + kb + n];
                    else if (f < 2 * DD)  r[q] = g_eT [(f - DD) * NTOT + kb + n];
                    else if (f < 70)      r[q] = g_hT [(f - 2 * DD) * NTOT + kb + n];
                    else                  r[q] = g_sq [kb + n];
                }
            }
        }
        int k = k0 + it * 32 + lane;
        float dot1 = 0.f, dot2 = 0.f, ed1 = 0.f, ed2 = 0.f;
        #pragma unroll
        for (int d = 0; d < DD; d++) {
            float xv = cur[d * 32 + lane];
            dot1 += cp1[d] * xv;  dot2 += cp2[d] * xv;
            float ev = cur[(DD + d) * 32 + lane];
            ed1 += ec1[d] * ev;   ed2 += ec2[d] * ev;
        }
        float sqk = cur[70 * 32 + lane];
        float t1 = om * (sq1 + sqk - 2.0f * dot1) + pm * ed1;
        float t2 = om * (sq2 + sqk - 2.0f * dot2) + pm * ed2;
        float a1 = (k == BN + ja) ? 1.0f : 1.0f / (t1 / 19.0f);
        float a2 = (k == BN + jb) ? 1.0f : 1.0f / (t2 / 19.0f);
        #pragma unroll
        for (int c = 0; c < HIDD; c++) {
            float hv = cur[(2 * DD + c) * 32 + lane];
            acc1[c] += a1 * hv;  acc2[c] += a2 * hv;
        }
        if (it < 16) {
            #pragma unroll
            for (int q = 0; q < 9; q++) {
                int idx = t + q * 256;
                if (idx < CHUNK) nxt[idx] = r[q];
            }
        }
        __syncthreads();
    }

    #pragma unroll
    for (int c = 0; c < HIDD; c++) {
        float v1 = acc1[c], v2 = acc2[c];
        #pragma unroll
        for (int o = 16; o; o >>= 1) {
            v1 += __shfl_xor_sync(0xffffffffu, v1, o);
            v2 += __shfl_xor_sync(0xffffffffu, v2, o);
        }
        if (lane == 0) {
            atomicAdd(&g_embpreT[c * NCC + ja], v1);
            atomicAdd(&g_embpreT[c * NCC + jb], v2);
        }
    }

    // ---- last emb block computes heads ----
    __threadfence();
    __syncthreads();
    if (t == 0) s_last = (atomicAdd(&g_ctr, 1) == 127) ? 1 : 0;
    __syncthreads();
    if (!s_last) return;

    float* s_ow = pool;            // 608
    float* s_ob = pool + 608;      // 19
    float* s_w1 = pool + 627;      // 304
    float* s_b1 = pool + 931;      // 16
    float* s_w2 = pool + 947;      // 304
    float* s_b2 = pool + 1251;     // 19
    float* s_gb = pool + 1270;     // 32
    __syncthreads();
    for (int i = t; i < HIDD * DD; i += 256) s_ow[i] = out_w[i];
    for (int i = t; i < DD * SQH; i += 256)  s_w1[i] = iw1[i];
    for (int i = t; i < SQH * DD; i += 256)  s_w2[i] = iw2[i];
    if (t < DD)   s_ob[t] = out_b[t];
    if (t < SQH)  s_b1[t] = ib1[t];
    if (t < DD)   s_b2[t] = ib2[t];
    if (t < HIDD) s_gb[t] = gcn_b[t];
    __syncthreads();

    int j = t;
    float v[HIDD];
    #pragma unroll
    for (int c = 0; c < HIDD; c++) v[c] = g_embpreT[c * NCC + j] + s_gb[c];
    float ge[DD];
    #pragma unroll
    for (int d = 0; d < DD; d++) {
        float s = s_ob[d];
        #pragma unroll
        for (int c = 0; c < HIDD; c++) s += v[c] * s_ow[c * DD + d];
        ge[d] = 1.0f / (1.0f + expf(-s));
        g_geT[d * NCC + j] = ge[d];
    }
    float h2[SQH];
    #pragma unroll
    for (int q = 0; q < SQH; q++) {
        float s = s_b1[q];
        #pragma unroll
        for (int d = 0; d < DD; d++) s += ge[d] * s_w1[d * SQH + q];
        h2[q] = 0.5f * s * (1.0f + erff(s * 0.70710678118654752440f));
    }
    #pragma unroll
    for (int d = 0; d < DD; d++) {
        float s = s_b2[d];
        #pragma unroll
        for (int q = 0; q < SQH; q++) s += h2[q] * s_w2[q * DD + d];
        g_spgT[d * NCC + j] = 1.0f / (1.0f + expf(-s));
    }
}

// ---------------------------------------------------------------------------
// out: [group_scores 4096x19 | group_embedding 256x19 |
//       group_patients_embedding 4096x19 | group_label 4096 as float]
__global__ void k_out(float* __restrict__ out) {
    int t = blockIdx.x * 256 + threadIdx.x;
    if (t < 77824) {
        int i = t / 19, d = t - i * 19;
        out[t] = g_spgT[d * NCC + g_label[i]];
    } else if (t < 82688) {
        int u = t - 77824; int j = u / 19, d = u - j * 19;
        out[t] = g_geT[d * NCC + j];
    } else if (t < 160512) {
        int u = t - 82688; int i = u / 19, d = u - i * 19;
        out[t] = g_geT[d * NCC + g_label[i]];
    } else {
        out[t] = (float)g_label[t - 160512];
    }
}

// ---------------------------------------------------------------------------
extern "C" void kernel_launch(void* const* d_in, const int* in_sizes, int n_in,
                              void* d_out, int out_size) {
    const float* x       = (const float*)d_in[0];
    const float* dc      = (const float*)d_in[1];
    const float* centers = (const float*)d_in[2];
    const float* proj_w  = (const float*)d_in[3];
    const float* proj_b  = (const float*)d_in[4];
    const float* dcp     = (const float*)d_in[5];
    const float* cc      = (const float*)d_in[6];
    const float* gcn_w   = (const float*)d_in[7];
    const float* gcn_b   = (const float*)d_in[8];
    const float* out_w   = (const float*)d_in[9];
    const float* out_b   = (const float*)d_in[10];
    const float* iw1     = (const float*)d_in[11];
    const float* ib1     = (const float*)d_in[12];
    const float* iw2     = (const float*)d_in[13];
    const float* ib2     = (const float*)d_in[14];
    float* out = (float*)d_out;

    k_xavg      <<<4881, 256>>>(x, dc, centers, proj_w, proj_b, cc, gcn_w);
    k_prep2     <<<16,   256>>>(gcn_w);
    k_argmax_emb<<<256,  256>>>(dcp, gcn_b, out_w, out_b, iw1, ib1, iw2, ib2);
    k_out       <<<643,  256>>>(out);
}